// round 16
// baseline (speedup 1.0000x reference)
#include <cuda_runtime.h>
#include <cuda_fp16.h>
#include <math.h>
#include <stdint.h>

// ---- problem constants ----
#define OC     128
#define IC     64
#define SPAN   576
#define TSIZE  8
#define MLSH   5
#define HH     56
#define WW     56
#define BATCH  16
#define IMG    (HH*WW)      // 3136
#define NPIX   (BATCH*IMG)  // 50176
#define NCHUNK 9

// ---- device scratch ----
__device__ int   g_counts[TSIZE];
__device__ float g_factor[OC];
__device__ __align__(16) uint4 g_Wfrag[NCHUNK * 2 * 4 * 4 * 32];
__device__ __align__(16) unsigned short g_xhi[NPIX * IC];

// ============================================================
// helpers
// ============================================================
__device__ __forceinline__ uint32_t smem_u32(const void* p) {
    uint32_t a;
    asm("{ .reg .u64 t; cvta.to.shared.u64 t, %1; cvt.u32.u64 %0, t; }" : "=r"(a) : "l"(p));
    return a;
}
__device__ __forceinline__ uint32_t swz(uint32_t off) { return off ^ ((off >> 3) & 0x70); }

__device__ __forceinline__ void ldsm_x4(uint32_t* r, uint32_t addr) {
    asm volatile("ldmatrix.sync.aligned.m8n8.x4.shared.b16 {%0,%1,%2,%3}, [%4];"
        : "=r"(r[0]), "=r"(r[1]), "=r"(r[2]), "=r"(r[3]) : "r"(addr));
}
__device__ __forceinline__ void mma_f16(float* c, const uint32_t* a, const uint32_t* b) {
    asm volatile(
        "mma.sync.aligned.m16n8k16.row.col.f32.f16.f16.f32 "
        "{%0,%1,%2,%3}, {%4,%5,%6,%7}, {%8,%9}, {%0,%1,%2,%3};"
        : "+f"(c[0]), "+f"(c[1]), "+f"(c[2]), "+f"(c[3])
        : "r"(a[0]), "r"(a[1]), "r"(a[2]), "r"(a[3]), "r"(b[0]), "r"(b[1]));
}
__device__ __forceinline__ void cp16(uint32_t dst, const void* src, int srcsize) {
    asm volatile("cp.async.ca.shared.global [%0], [%1], 16, %2;"
        :: "r"(dst), "l"(src), "r"(srcsize) : "memory");
}

__device__ __forceinline__ int bucket_of(float h, float b) {
    float q = floorf((h + b) / 2.5f);
    int i = (int)q;
    int r = i % TSIZE;
    return r < 0 ? -r : r;
}
__device__ __forceinline__ uint32_t pack2h(float a, float b) {
    return (uint32_t)__half_as_ushort(__float2half_rn(a))
         | ((uint32_t)__half_as_ushort(__float2half_rn(b)) << 16);
}

// ------------------------------------------------------------------
// prep_w: fp16 fragments, PERMUTED k; block 0 also zeroes g_counts
// ------------------------------------------------------------------
__global__ __launch_bounds__(256) void prep_w_kernel(const float* __restrict__ W) {
    if (blockIdx.x == 0 && threadIdx.x < TSIZE) g_counts[threadIdx.x] = 0;

    int i = blockIdx.x * 256 + threadIdx.x;
    int lane = i & 31;
    int ks   = (i >> 5) & 3;
    int mt   = (i >> 7) & 3;
    int wm   = (i >> 9) & 1;
    int ch   = i >> 10;

    int r   = wm * 64 + mt * 16 + (lane >> 2);
    int pos = ks * 16 + (lane & 3) * 2;

    const float* Wr  = W + (size_t)r * SPAN + ch;
    const float* Wr8 = Wr + 8 * SPAN;

    uint4 hi = make_uint4(
        pack2h(Wr[pos * 9],        Wr[(pos + 1) * 9]),
        pack2h(Wr8[pos * 9],       Wr8[(pos + 1) * 9]),
        pack2h(Wr[(pos + 8) * 9],  Wr[(pos + 9) * 9]),
        pack2h(Wr8[(pos + 8) * 9], Wr8[(pos + 9) * 9]));

    g_Wfrag[(((ch * 2 + wm) * 4 + mt) * 4 + ks) * 32 + lane] = hi;
}

// ------------------------------------------------------------------
// Fused vote + x-transpose, float4 staging.
// smem rows PW=64 wide; x data at cols [4,60), zero borders at 3 / 60.
// ------------------------------------------------------------------
#define PWV 64
#define VOTE_SMEM (IC * 3 * PWV * 4)      // 48 KB dynamic

__global__ __launch_bounds__(256) void vote_kernel(
    const float* __restrict__ x, const float* __restrict__ a, const float* __restrict__ bptr)
{
    extern __shared__ float sx[];          // [c][r][PWV]
    __shared__ float sa[SPAN + MLSH];
    __shared__ float partial[WW][4];
    __shared__ int hist[TSIZE];

    const int tid = threadIdx.x;
    const int b   = blockIdx.x / HH;
    const int y   = blockIdx.x % HH;

    for (int i = tid; i < SPAN + MLSH; i += 256) sa[i] = a[i];
    if (tid < TSIZE) hist[tid] = 0;

    // ---- float4 staging: IC*3*14 = 2688 vec loads ----
    const float* xb = x + (size_t)b * IC * IMG;
    #pragma unroll 4
    for (int idx = tid; idx < IC * 3 * 14; idx += 256) {
        int c   = idx / 42;
        int rem = idx - c * 42;
        int r   = rem / 14;
        int q   = rem - r * 14;
        int yy  = y + r - 1;
        float4 v = make_float4(0.f, 0.f, 0.f, 0.f);
        if ((unsigned)yy < HH)
            v = *(const float4*)(xb + (size_t)c * IMG + yy * WW + 4 * q);
        *(float4*)(sx + (c * 3 + r) * PWV + 4 + 4 * q) = v;
    }
    // zero borders (cols 3 and 60 of each row)
    if (tid < IC * 3) { sx[tid * PWV + 3] = 0.0f; sx[tid * PWV + 60] = 0.0f; }
    __syncthreads();

    // ---- fused transpose of row y (r=1 plane) to channel-last fp16 ----
    {
        uint32_t* dhi = (uint32_t*)g_xhi + (size_t)(b * IMG + y * WW) * 32;
        for (int idx = tid; idx < WW * 32; idx += 256) {
            int xx = idx >> 5, w = idx & 31;
            float v0 = sx[(2 * w)     * (3 * PWV) + PWV + 4 + xx];
            float v1 = sx[(2 * w + 1) * (3 * PWV) + PWV + 4 + xx];
            dhi[xx * 32 + w] = pack2h(v0, v1);
        }
    }

    // ---- vote compute ----
    const int g  = tid >> 6;
    const int xx = tid & 63;
    if (xx < WW) {
        float v0 = 0.0f, v1 = 0.0f, v2 = 0.0f;
        const float* base0 = sx + (g * 16) * (3 * PWV) + xx + 4;
        const float* sac0  = sa + (g * 16) * 9;
        #pragma unroll 4
        for (int ci = 0; ci < 16; ci++) {
            const float* basec = base0 + ci * (3 * PWV);
            const float* sac   = sac0 + ci * 9;
            #pragma unroll
            for (int dx = 0; dx < 3; dx++) {
                v0 += sac[dx]     * basec[dx - 1];
                v1 += sac[3 + dx] * basec[PWV + dx - 1];
                v2 += sac[6 + dx] * basec[2 * PWV + dx - 1];
            }
        }
        partial[xx][g] = v0 + v1 + v2;
    }
    __syncthreads();

    if (tid < WW) {
        float v = partial[tid][0] + partial[tid][1] + partial[tid][2] + partial[tid][3];
        float q = 0.0f;
        #pragma unroll
        for (int i = 0; i < MLSH; i++) q += sa[SPAN + i];
        v += 0.5f * q;
        atomicAdd(&hist[bucket_of(v, bptr[0])], 1);
    }
    __syncthreads();
    if (tid < TSIZE) atomicAdd(&g_counts[tid], hist[tid]);
}

// ------------------------------------------------------------------
// Factor pass
// ------------------------------------------------------------------
__global__ __launch_bounds__(128) void factor_kernel(
    const float* __restrict__ kernels, const float* __restrict__ a, const float* __restrict__ bptr)
{
    __shared__ float sa[SPAN + MLSH];
    __shared__ int sh_bucket, sh_cnt;
    for (int i = threadIdx.x; i < SPAN + MLSH; i += blockDim.x) sa[i] = a[i];
    if (threadIdx.x == 0) {
        int best = 0, bi = 0;
        #pragma unroll
        for (int t = 0; t < TSIZE; t++) { int c = g_counts[t]; if (c > best) { best = c; bi = t; } }
        sh_bucket = bi; sh_cnt = 0;
    }
    __syncthreads();

    int oc = threadIdx.x;
    const float* w = kernels + (size_t)oc * SPAN;
    float dot = 0.0f, nrm = 0.0f;
    for (int k = 0; k < SPAN; k++) { float wv = w[k]; dot += wv * sa[k]; nrm += wv * wv; }
    float s = nrm, paug = 0.0f;
    #pragma unroll
    for (int i = 0; i < MLSH; i++) { paug += s * sa[SPAN + i]; s = s * s; }
    int kidx = bucket_of(dot + paug, bptr[0]);
    int in_bucket = (kidx == sh_bucket) ? 1 : 0;
    atomicAdd(&sh_cnt, in_bucket);
    __syncthreads();
    int cnt = sh_cnt;
    g_factor[oc] = (cnt > 0) ? (in_bucket ? ((float)OC / (float)cnt) : 0.0f) : 1.0f;
}

// ------------------------------------------------------------------
// HMMA conv GEMM (unchanged from R15): fp16 single pass, A reg
// pipeline, B staged 2 chunks ahead via cp.async 3-stage ring.
// ------------------------------------------------------------------
#define BN        64
#define STAGE     8192
#define DYN_SMEM  (3*STAGE + 1024)

__device__ __forceinline__ void stage_tap(uint32_t stage_u, uint32_t row_off, int kbase,
                                          const unsigned short* hi_src, int srcsize) {
    #pragma unroll
    for (int p = 0; p < 2; p++) {
        uint32_t addr = swz(row_off + (uint32_t)(kbase + p * 8) * 2);
        cp16(stage_u + addr, hi_src + p * 8, srcsize);
    }
}

struct AF { uint4 m0, m1; };
__device__ __forceinline__ AF ldA(const uint4* __restrict__ Af, int idx) {
    AF r;
    r.m0 = Af[idx * 32];
    r.m1 = Af[(4 * 32) + idx * 32];
    return r;
}

__global__ __launch_bounds__(256, 3)
void conv_hmma_kernel(float* __restrict__ out)
{
    extern __shared__ char dsm[];
    char* sb = (char*)(((uintptr_t)dsm + 1023) & ~(uintptr_t)1023);
    const uint32_t sb_u = smem_u32(sb);

    const int tid  = threadIdx.x;
    const int wid  = tid >> 5;
    const int lane = tid & 31;
    const int n0   = blockIdx.x * BN;

    const int wm = wid >> 1;
    const int wn = wid & 1;

    const int rown  = tid >> 2;
    const int kbase = (tid & 3) * 16;
    const int n     = n0 + rown;
    const int bimg  = n / IMG;
    const int pix   = n - bimg * IMG;
    const int y0    = pix / WW;
    const int x0    = pix - y0 * WW;
    const unsigned short* xhi_b = g_xhi + (size_t)bimg * IMG * IC + kbase;
    const uint32_t row_off = (uint32_t)rown * 128;

    const uint32_t b_row = (uint32_t)(wn * 32 + (lane & 7) + ((lane >> 4) << 3)) * 128
                         + (((lane >> 3) & 1) << 4);

    const uint4* AfW = g_Wfrag + (wm >> 1) * 512 + (wm & 1) * 256 + lane;

    float acc[2][4][4];
    #pragma unroll
    for (int i = 0; i < 2; i++)
        #pragma unroll
        for (int j = 0; j < 4; j++)
            #pragma unroll
            for (int q = 0; q < 4; q++) acc[i][j][q] = 0.0f;

    #pragma unroll
    for (int c0 = 0; c0 < 2; c0++) {
        const int dyn = c0 / 3, dxn = c0 - dyn * 3;
        const int yy = y0 + dyn - 1, xx = x0 + dxn - 1;
        const bool valid = ((unsigned)yy < HH) && ((unsigned)xx < WW);
        const int tap = valid ? (yy * WW + xx) : 0;
        stage_tap(sb_u + (uint32_t)c0 * STAGE, row_off, kbase,
                  xhi_b + (size_t)tap * IC, valid ? 16 : 0);
        asm volatile("cp.async.commit_group;" ::: "memory");
    }
    AF aNext = ldA(AfW, 0);

    for (int ch = 0; ch < NCHUNK; ch++) {
        if (ch < NCHUNK - 1) {
            asm volatile("cp.async.wait_group 1;" ::: "memory");
        } else {
            asm volatile("cp.async.wait_group 0;" ::: "memory");
        }
        __syncthreads();

        const int chs = ch + 2;
        if (chs < NCHUNK) {
            const int dyn = chs / 3, dxn = chs - dyn * 3;
            const int yy  = y0 + dyn - 1, xx = x0 + dxn - 1;
            const bool valid = ((unsigned)yy < HH) && ((unsigned)xx < WW);
            const int tap = valid ? (yy * WW + xx) : 0;
            stage_tap(sb_u + (uint32_t)(chs % 3) * STAGE, row_off, kbase,
                      xhi_b + (size_t)tap * IC, valid ? 16 : 0);
            asm volatile("cp.async.commit_group;" ::: "memory");
        }

        const uint32_t cur_u = sb_u + (uint32_t)(ch % 3) * STAGE;
        const uint4* Af = AfW + ch * 1024;

        #pragma unroll
        for (int ks = 0; ks < 4; ks++) {
            AF aCur = aNext;
            if (!(ch == NCHUNK - 1 && ks == 3)) {
                const uint4* AfN = (ks == 3) ? (Af + 1024) : Af;
                aNext = ldA(AfN, (ks == 3) ? 0 : ks + 1);
            }

            const uint32_t kb = (uint32_t)ks * 32;
            uint32_t bhf[4][2];
            #pragma unroll
            for (int p = 0; p < 2; p++) {
                uint32_t t[4];
                ldsm_x4(t, cur_u + swz(b_row + (uint32_t)p * 2048 + kb));
                bhf[p*2+0][0] = t[0]; bhf[p*2+0][1] = t[1];
                bhf[p*2+1][0] = t[2]; bhf[p*2+1][1] = t[3];
            }
            #pragma unroll
            for (int nt = 0; nt < 4; nt++) {
                mma_f16(acc[0][nt], (const uint32_t*)&aCur.m0, bhf[nt]);
                mma_f16(acc[1][nt], (const uint32_t*)&aCur.m1, bhf[nt]);
            }
        }
    }

    #pragma unroll
    for (int mt = 0; mt < 2; mt++) {
        const int m0 = wm * 32 + mt * 16 + (lane >> 2);
        const float f0 = g_factor[m0];
        const float f1 = g_factor[m0 + 8];
        #pragma unroll
        for (int nt = 0; nt < 4; nt++) {
            const int np = n0 + wn * 32 + nt * 8 + (lane & 3) * 2;
            const int bb = np / IMG;
            const int pp = np - bb * IMG;
            float* o0 = out + ((size_t)bb * OC + m0) * IMG + pp;
            *(float2*)o0             = make_float2(acc[mt][nt][0] * f0, acc[mt][nt][1] * f0);
            *(float2*)(o0 + 8 * IMG) = make_float2(acc[mt][nt][2] * f1, acc[mt][nt][3] * f1);
        }
    }
}

// ------------------------------------------------------------------
extern "C" void kernel_launch(void* const* d_in, const int* in_sizes, int n_in,
                              void* d_out, int out_size)
{
    const float* x       = (const float*)d_in[0];
    const float* kernels = (const float*)d_in[1];
    const float* a       = (const float*)d_in[2];
    const float* b       = (const float*)d_in[3];
    float* out = (float*)d_out;

    static bool attr_set = false;
    if (!attr_set) {
        cudaFuncSetAttribute(conv_hmma_kernel,
                             cudaFuncAttributeMaxDynamicSharedMemorySize, DYN_SMEM);
        cudaFuncSetAttribute(vote_kernel,
                             cudaFuncAttributeMaxDynamicSharedMemorySize, VOTE_SMEM);
        attr_set = true;
    }

    prep_w_kernel<<<36, 256>>>(kernels);                    // also zeroes g_counts
    vote_kernel<<<BATCH * HH, 256, VOTE_SMEM>>>(x, a, b);   // also writes g_xhi
    factor_kernel<<<1, 128>>>(kernels, a, b);
    conv_hmma_kernel<<<NPIX / BN, 256, DYN_SMEM>>>(out);
}

// round 17
// speedup vs baseline: 1.1618x; 1.1618x over previous
#include <cuda_runtime.h>
#include <cuda_fp16.h>
#include <math.h>
#include <stdint.h>

// ---- problem constants ----
#define OC     128
#define IC     64
#define SPAN   576
#define TSIZE  8
#define MLSH   5
#define HH     56
#define WW     56
#define BATCH  16
#define IMG    (HH*WW)      // 3136
#define NPIX   (BATCH*IMG)  // 50176
#define NCHUNK 9

// ---- device scratch ----
__device__ int   g_counts[TSIZE];
__device__ float g_factor[OC];
__device__ __align__(16) uint4 g_Wfrag[NCHUNK * 2 * 4 * 4 * 32];
__device__ __align__(16) unsigned short g_xhi[NPIX * IC];

// ============================================================
// helpers
// ============================================================
__device__ __forceinline__ uint32_t smem_u32(const void* p) {
    uint32_t a;
    asm("{ .reg .u64 t; cvta.to.shared.u64 t, %1; cvt.u32.u64 %0, t; }" : "=r"(a) : "l"(p));
    return a;
}
__device__ __forceinline__ uint32_t swz(uint32_t off) { return off ^ ((off >> 3) & 0x70); }

__device__ __forceinline__ void ldsm_x4(uint32_t* r, uint32_t addr) {
    asm volatile("ldmatrix.sync.aligned.m8n8.x4.shared.b16 {%0,%1,%2,%3}, [%4];"
        : "=r"(r[0]), "=r"(r[1]), "=r"(r[2]), "=r"(r[3]) : "r"(addr));
}
__device__ __forceinline__ void mma_f16(float* c, const uint32_t* a, const uint32_t* b) {
    asm volatile(
        "mma.sync.aligned.m16n8k16.row.col.f32.f16.f16.f32 "
        "{%0,%1,%2,%3}, {%4,%5,%6,%7}, {%8,%9}, {%0,%1,%2,%3};"
        : "+f"(c[0]), "+f"(c[1]), "+f"(c[2]), "+f"(c[3])
        : "r"(a[0]), "r"(a[1]), "r"(a[2]), "r"(a[3]), "r"(b[0]), "r"(b[1]));
}
__device__ __forceinline__ void cp16(uint32_t dst, const void* src, int srcsize) {
    asm volatile("cp.async.ca.shared.global [%0], [%1], 16, %2;"
        :: "r"(dst), "l"(src), "r"(srcsize) : "memory");
}

__device__ __forceinline__ int bucket_of(float h, float b) {
    float q = floorf((h + b) / 2.5f);
    int i = (int)q;
    int r = i % TSIZE;
    return r < 0 ? -r : r;
}
__device__ __forceinline__ uint32_t pack2h(float a, float b) {
    return (uint32_t)__half_as_ushort(__float2half_rn(a))
         | ((uint32_t)__half_as_ushort(__float2half_rn(b)) << 16);
}

// ------------------------------------------------------------------
// prep_w: fp16 fragments, PERMUTED k; block 0 also zeroes g_counts
// ------------------------------------------------------------------
__global__ __launch_bounds__(256) void prep_w_kernel(const float* __restrict__ W) {
    if (blockIdx.x == 0 && threadIdx.x < TSIZE) g_counts[threadIdx.x] = 0;

    int i = blockIdx.x * 256 + threadIdx.x;
    int lane = i & 31;
    int ks   = (i >> 5) & 3;
    int mt   = (i >> 7) & 3;
    int wm   = (i >> 9) & 1;
    int ch   = i >> 10;

    int r   = wm * 64 + mt * 16 + (lane >> 2);
    int pos = ks * 16 + (lane & 3) * 2;

    const float* Wr  = W + (size_t)r * SPAN + ch;
    const float* Wr8 = Wr + 8 * SPAN;

    uint4 hi = make_uint4(
        pack2h(Wr[pos * 9],        Wr[(pos + 1) * 9]),
        pack2h(Wr8[pos * 9],       Wr8[(pos + 1) * 9]),
        pack2h(Wr[(pos + 8) * 9],  Wr[(pos + 9) * 9]),
        pack2h(Wr8[(pos + 8) * 9], Wr8[(pos + 9) * 9]));

    g_Wfrag[(((ch * 2 + wm) * 4 + mt) * 4 + ks) * 32 + lane] = hi;
}

// ------------------------------------------------------------------
// Fused vote + x-transpose; R15 smem layout (PW=58, 4-way-conflict
// transpose), but staging via float4 LDG + scalar STS (high MLP).
// ------------------------------------------------------------------
#define PW 58
__global__ __launch_bounds__(256) void vote_kernel(
    const float* __restrict__ x, const float* __restrict__ a, const float* __restrict__ bptr)
{
    __shared__ float sx[IC * 3 * PW];
    __shared__ float sa[SPAN + MLSH];
    __shared__ float partial[WW][4];
    __shared__ int hist[TSIZE];

    const int tid = threadIdx.x;
    const int b   = blockIdx.x / HH;
    const int y   = blockIdx.x % HH;

    for (int i = tid; i < SPAN + MLSH; i += 256) sa[i] = a[i];
    if (tid < TSIZE) hist[tid] = 0;

    // ---- staging: float4 LDG (MLP), scalar STS into PW=58 rows ----
    // cols [1,57) hold x; borders 0 and 57 zeroed.
    const float* xb = x + (size_t)b * IC * IMG;
    #pragma unroll 4
    for (int idx = tid; idx < IC * 3 * 14; idx += 256) {
        int c   = idx / 42;
        int rem = idx - c * 42;
        int r   = rem / 14;
        int q   = rem - r * 14;
        int yy  = y + r - 1;
        float4 v = make_float4(0.f, 0.f, 0.f, 0.f);
        if ((unsigned)yy < HH)
            v = *(const float4*)(xb + (size_t)c * IMG + yy * WW + 4 * q);
        float* dst = sx + (c * 3 + r) * PW + 1 + 4 * q;
        dst[0] = v.x; dst[1] = v.y; dst[2] = v.z; dst[3] = v.w;
    }
    if (tid < IC * 3) { sx[tid * PW] = 0.0f; sx[tid * PW + 57] = 0.0f; }
    __syncthreads();

    // ---- fused transpose of row y (r=1 plane) to channel-last fp16 ----
    {
        uint32_t* dhi = (uint32_t*)g_xhi + (size_t)(b * IMG + y * WW) * 32;
        for (int idx = tid; idx < WW * 32; idx += 256) {
            int xx = idx >> 5, w = idx & 31;
            float v0 = sx[(2 * w)     * (3 * PW) + PW + 1 + xx];
            float v1 = sx[(2 * w + 1) * (3 * PW) + PW + 1 + xx];
            dhi[xx * 32 + w] = pack2h(v0, v1);
        }
    }

    // ---- vote compute ----
    const int g  = tid >> 6;
    const int xx = tid & 63;
    if (xx < WW) {
        float v0 = 0.0f, v1 = 0.0f, v2 = 0.0f;
        const float* base0 = sx + (g * 16) * (3 * PW) + xx;
        const float* sac0  = sa + (g * 16) * 9;
        #pragma unroll 4
        for (int ci = 0; ci < 16; ci++) {
            const float* basec = base0 + ci * (3 * PW);
            const float* sac   = sac0 + ci * 9;
            #pragma unroll
            for (int dx = 0; dx < 3; dx++) {
                v0 += sac[dx]     * basec[dx];
                v1 += sac[3 + dx] * basec[PW + dx];
                v2 += sac[6 + dx] * basec[2 * PW + dx];
            }
        }
        partial[xx][g] = v0 + v1 + v2;
    }
    __syncthreads();

    if (tid < WW) {
        float v = partial[tid][0] + partial[tid][1] + partial[tid][2] + partial[tid][3];
        float q = 0.0f;
        #pragma unroll
        for (int i = 0; i < MLSH; i++) q += sa[SPAN + i];
        v += 0.5f * q;
        atomicAdd(&hist[bucket_of(v, bptr[0])], 1);
    }
    __syncthreads();
    if (tid < TSIZE) atomicAdd(&g_counts[tid], hist[tid]);
}

// ------------------------------------------------------------------
// Factor pass
// ------------------------------------------------------------------
__global__ __launch_bounds__(128) void factor_kernel(
    const float* __restrict__ kernels, const float* __restrict__ a, const float* __restrict__ bptr)
{
    __shared__ float sa[SPAN + MLSH];
    __shared__ int sh_bucket, sh_cnt;
    for (int i = threadIdx.x; i < SPAN + MLSH; i += blockDim.x) sa[i] = a[i];
    if (threadIdx.x == 0) {
        int best = 0, bi = 0;
        #pragma unroll
        for (int t = 0; t < TSIZE; t++) { int c = g_counts[t]; if (c > best) { best = c; bi = t; } }
        sh_bucket = bi; sh_cnt = 0;
    }
    __syncthreads();

    int oc = threadIdx.x;
    const float* w = kernels + (size_t)oc * SPAN;
    float dot = 0.0f, nrm = 0.0f;
    for (int k = 0; k < SPAN; k++) { float wv = w[k]; dot += wv * sa[k]; nrm += wv * wv; }
    float s = nrm, paug = 0.0f;
    #pragma unroll
    for (int i = 0; i < MLSH; i++) { paug += s * sa[SPAN + i]; s = s * s; }
    int kidx = bucket_of(dot + paug, bptr[0]);
    int in_bucket = (kidx == sh_bucket) ? 1 : 0;
    atomicAdd(&sh_cnt, in_bucket);
    __syncthreads();
    int cnt = sh_cnt;
    g_factor[oc] = (cnt > 0) ? (in_bucket ? ((float)OC / (float)cnt) : 0.0f) : 1.0f;
}

// ------------------------------------------------------------------
// HMMA conv GEMM (unchanged from R15)
// ------------------------------------------------------------------
#define BN        64
#define STAGE     8192
#define DYN_SMEM  (3*STAGE + 1024)

__device__ __forceinline__ void stage_tap(uint32_t stage_u, uint32_t row_off, int kbase,
                                          const unsigned short* hi_src, int srcsize) {
    #pragma unroll
    for (int p = 0; p < 2; p++) {
        uint32_t addr = swz(row_off + (uint32_t)(kbase + p * 8) * 2);
        cp16(stage_u + addr, hi_src + p * 8, srcsize);
    }
}

struct AF { uint4 m0, m1; };
__device__ __forceinline__ AF ldA(const uint4* __restrict__ Af, int idx) {
    AF r;
    r.m0 = Af[idx * 32];
    r.m1 = Af[(4 * 32) + idx * 32];
    return r;
}

__global__ __launch_bounds__(256, 3)
void conv_hmma_kernel(float* __restrict__ out)
{
    extern __shared__ char dsm[];
    char* sb = (char*)(((uintptr_t)dsm + 1023) & ~(uintptr_t)1023);
    const uint32_t sb_u = smem_u32(sb);

    const int tid  = threadIdx.x;
    const int wid  = tid >> 5;
    const int lane = tid & 31;
    const int n0   = blockIdx.x * BN;

    const int wm = wid >> 1;
    const int wn = wid & 1;

    const int rown  = tid >> 2;
    const int kbase = (tid & 3) * 16;
    const int n     = n0 + rown;
    const int bimg  = n / IMG;
    const int pix   = n - bimg * IMG;
    const int y0    = pix / WW;
    const int x0    = pix - y0 * WW;
    const unsigned short* xhi_b = g_xhi + (size_t)bimg * IMG * IC + kbase;
    const uint32_t row_off = (uint32_t)rown * 128;

    const uint32_t b_row = (uint32_t)(wn * 32 + (lane & 7) + ((lane >> 4) << 3)) * 128
                         + (((lane >> 3) & 1) << 4);

    const uint4* AfW = g_Wfrag + (wm >> 1) * 512 + (wm & 1) * 256 + lane;

    float acc[2][4][4];
    #pragma unroll
    for (int i = 0; i < 2; i++)
        #pragma unroll
        for (int j = 0; j < 4; j++)
            #pragma unroll
            for (int q = 0; q < 4; q++) acc[i][j][q] = 0.0f;

    #pragma unroll
    for (int c0 = 0; c0 < 2; c0++) {
        const int dyn = c0 / 3, dxn = c0 - dyn * 3;
        const int yy = y0 + dyn - 1, xx = x0 + dxn - 1;
        const bool valid = ((unsigned)yy < HH) && ((unsigned)xx < WW);
        const int tap = valid ? (yy * WW + xx) : 0;
        stage_tap(sb_u + (uint32_t)c0 * STAGE, row_off, kbase,
                  xhi_b + (size_t)tap * IC, valid ? 16 : 0);
        asm volatile("cp.async.commit_group;" ::: "memory");
    }
    AF aNext = ldA(AfW, 0);

    for (int ch = 0; ch < NCHUNK; ch++) {
        if (ch < NCHUNK - 1) {
            asm volatile("cp.async.wait_group 1;" ::: "memory");
        } else {
            asm volatile("cp.async.wait_group 0;" ::: "memory");
        }
        __syncthreads();

        const int chs = ch + 2;
        if (chs < NCHUNK) {
            const int dyn = chs / 3, dxn = chs - dyn * 3;
            const int yy  = y0 + dyn - 1, xx = x0 + dxn - 1;
            const bool valid = ((unsigned)yy < HH) && ((unsigned)xx < WW);
            const int tap = valid ? (yy * WW + xx) : 0;
            stage_tap(sb_u + (uint32_t)(chs % 3) * STAGE, row_off, kbase,
                      xhi_b + (size_t)tap * IC, valid ? 16 : 0);
            asm volatile("cp.async.commit_group;" ::: "memory");
        }

        const uint32_t cur_u = sb_u + (uint32_t)(ch % 3) * STAGE;
        const uint4* Af = AfW + ch * 1024;

        #pragma unroll
        for (int ks = 0; ks < 4; ks++) {
            AF aCur = aNext;
            if (!(ch == NCHUNK - 1 && ks == 3)) {
                const uint4* AfN = (ks == 3) ? (Af + 1024) : Af;
                aNext = ldA(AfN, (ks == 3) ? 0 : ks + 1);
            }

            const uint32_t kb = (uint32_t)ks * 32;
            uint32_t bhf[4][2];
            #pragma unroll
            for (int p = 0; p < 2; p++) {
                uint32_t t[4];
                ldsm_x4(t, cur_u + swz(b_row + (uint32_t)p * 2048 + kb));
                bhf[p*2+0][0] = t[0]; bhf[p*2+0][1] = t[1];
                bhf[p*2+1][0] = t[2]; bhf[p*2+1][1] = t[3];
            }
            #pragma unroll
            for (int nt = 0; nt < 4; nt++) {
                mma_f16(acc[0][nt], (const uint32_t*)&aCur.m0, bhf[nt]);
                mma_f16(acc[1][nt], (const uint32_t*)&aCur.m1, bhf[nt]);
            }
        }
    }

    #pragma unroll
    for (int mt = 0; mt < 2; mt++) {
        const int m0 = wm * 32 + mt * 16 + (lane >> 2);
        const float f0 = g_factor[m0];
        const float f1 = g_factor[m0 + 8];
        #pragma unroll
        for (int nt = 0; nt < 4; nt++) {
            const int np = n0 + wn * 32 + nt * 8 + (lane & 3) * 2;
            const int bb = np / IMG;
            const int pp = np - bb * IMG;
            float* o0 = out + ((size_t)bb * OC + m0) * IMG + pp;
            *(float2*)o0             = make_float2(acc[mt][nt][0] * f0, acc[mt][nt][1] * f0);
            *(float2*)(o0 + 8 * IMG) = make_float2(acc[mt][nt][2] * f1, acc[mt][nt][3] * f1);
        }
    }
}

// ------------------------------------------------------------------
extern "C" void kernel_launch(void* const* d_in, const int* in_sizes, int n_in,
                              void* d_out, int out_size)
{
    const float* x       = (const float*)d_in[0];
    const float* kernels = (const float*)d_in[1];
    const float* a       = (const float*)d_in[2];
    const float* b       = (const float*)d_in[3];
    float* out = (float*)d_out;

    static bool attr_set = false;
    if (!attr_set) {
        cudaFuncSetAttribute(conv_hmma_kernel,
                             cudaFuncAttributeMaxDynamicSharedMemorySize, DYN_SMEM);
        attr_set = true;
    }

    prep_w_kernel<<<36, 256>>>(kernels);                // also zeroes g_counts
    vote_kernel<<<BATCH * HH, 256>>>(x, a, b);          // also writes g_xhi
    factor_kernel<<<1, 128>>>(kernels, a, b);
    conv_hmma_kernel<<<NPIX / BN, 256, DYN_SMEM>>>(out);
}